// round 9
// baseline (speedup 1.0000x reference)
#include <cuda_runtime.h>
#include <math.h>
#include <mma.h>

using namespace nvcuda;

#define N_NODES 8192
#define P_META 3
#define IN_F 256
#define HIDD 64
#define N_HEADS 8
#define HD 512
#define OUT_F 64
#define NE 262144

// ---------------- scratch (static device allocations; no runtime alloc) ----
__device__ float d_feat[P_META][N_NODES * HD];    // 48 MB
__device__ float d_zp[P_META][N_NODES * HD];      // 48 MB
__device__ float d_el[P_META][N_NODES * N_HEADS];
__device__ float d_er[P_META][N_NODES * N_HEADS];
__device__ float d_invd[P_META][N_NODES * N_HEADS];
__device__ int   d_counts[P_META][N_NODES];
__device__ int   d_cursor[P_META][N_NODES];
__device__ int   d_offsets[P_META][N_NODES + 1];
__device__ int   d_csrsrc[P_META][NE];
__device__ float d_wsum[P_META];
__device__ float d_beta[P_META];
__device__ float d_v[HD];
__device__ float d_c;
__device__ float d_z[N_NODES * HD];

// ---------------------------------------------------------------- utilities
__global__ void zero_misc_kernel() {
    int p = blockIdx.y;
    int i = blockIdx.x * blockDim.x + threadIdx.x;
    if (i < N_NODES) d_counts[p][i] = 0;
    if (p == 0 && i < P_META) d_wsum[i] = 0.f;
}

__global__ void zero_atten_kernel(float4* a) {
    int i = blockIdx.x * blockDim.x + threadIdx.x;
    a[i] = make_float4(0.f, 0.f, 0.f, 0.f);
}

__device__ __forceinline__ float f2tf32(float x) {
    float r;
    asm("cvt.rna.tf32.f32 %0, %1;" : "=f"(r) : "f"(x));
    return r;
}

// ------------------------------------------------ feat = h @ fc_p (3xTF32 wmma)
// Block tile 128x128, 8 warps as 2(M)x4(N), warp tile 64x32.
// D = Ahi*Bhi + Ahi*Blo + Alo*Bhi  (error ~2^-22, effectively fp32)
__global__ void __launch_bounds__(256)
gemm_feat_tf32_kernel(const float* __restrict__ A,    // [8192,256]
                      const float* __restrict__ fc) { // [P,256,512]
    const int p = blockIdx.z;
    const float* __restrict__ B = fc + (size_t)p * IN_F * HD;
    float* __restrict__ C = d_feat[p];

    __shared__ float AsH[8][128];   // A^T: [k][m]
    __shared__ float AsL[8][128];
    __shared__ float BsH[8][128];   // [k][n]
    __shared__ float BsL[8][128];

    const int bm = blockIdx.y * 128;
    const int bn = blockIdx.x * 128;
    const int t = threadIdx.x;
    const int wid = t >> 5;
    const int wm = (wid & 1) * 64;   // warp M offset in tile
    const int wn = (wid >> 1) * 32;  // warp N offset in tile

    wmma::fragment<wmma::accumulator, 16, 16, 8, float> acc[4][2];
#pragma unroll
    for (int i = 0; i < 4; i++)
#pragma unroll
        for (int j = 0; j < 2; j++) wmma::fill_fragment(acc[i][j], 0.f);

    // loader indices
    const int a_m = t >> 1;             // 0..127
    const int a_k = (t & 1) * 4;        // 0 or 4
    const int b_k = t >> 5;             // 0..7
    const int b_n = (t & 31) * 4;       // 0..124

    for (int k0 = 0; k0 < IN_F; k0 += 8) {
        __syncthreads();
        // load + split A (128m x 8k), store transposed [k][m]
        {
            float4 v = *(const float4*)&A[(size_t)(bm + a_m) * IN_F + k0 + a_k];
            float h0 = f2tf32(v.x), h1 = f2tf32(v.y), h2 = f2tf32(v.z), h3 = f2tf32(v.w);
            AsH[a_k + 0][a_m] = h0; AsL[a_k + 0][a_m] = v.x - h0;
            AsH[a_k + 1][a_m] = h1; AsL[a_k + 1][a_m] = v.y - h1;
            AsH[a_k + 2][a_m] = h2; AsL[a_k + 2][a_m] = v.z - h2;
            AsH[a_k + 3][a_m] = h3; AsL[a_k + 3][a_m] = v.w - h3;
        }
        // load + split B (8k x 128n), store [k][n]
        {
            float4 v = *(const float4*)&B[(size_t)(k0 + b_k) * HD + bn + b_n];
            float h0 = f2tf32(v.x), h1 = f2tf32(v.y), h2 = f2tf32(v.z), h3 = f2tf32(v.w);
            *(float4*)&BsH[b_k][b_n] = make_float4(h0, h1, h2, h3);
            *(float4*)&BsL[b_k][b_n] = make_float4(v.x - h0, v.y - h1, v.z - h2, v.w - h3);
        }
        __syncthreads();

        wmma::fragment<wmma::matrix_a, 16, 16, 8, wmma::precision::tf32, wmma::col_major> aH[4], aL[4];
#pragma unroll
        for (int i = 0; i < 4; i++) {
            wmma::load_matrix_sync(aH[i], &AsH[0][wm + i * 16], 128);
            wmma::load_matrix_sync(aL[i], &AsL[0][wm + i * 16], 128);
#pragma unroll
            for (int e = 0; e < aH[i].num_elements; e++) {
                aH[i].x[e] = wmma::__float_to_tf32(aH[i].x[e]);
                aL[i].x[e] = wmma::__float_to_tf32(aL[i].x[e]);
            }
        }
#pragma unroll
        for (int j = 0; j < 2; j++) {
            wmma::fragment<wmma::matrix_b, 16, 16, 8, wmma::precision::tf32, wmma::row_major> bH, bL;
            wmma::load_matrix_sync(bH, &BsH[0][wn + j * 16], 128);
            wmma::load_matrix_sync(bL, &BsL[0][wn + j * 16], 128);
#pragma unroll
            for (int e = 0; e < bH.num_elements; e++) {
                bH.x[e] = wmma::__float_to_tf32(bH.x[e]);
                bL.x[e] = wmma::__float_to_tf32(bL.x[e]);
            }
#pragma unroll
            for (int i = 0; i < 4; i++) {
                wmma::mma_sync(acc[i][j], aH[i], bH, acc[i][j]);
                wmma::mma_sync(acc[i][j], aH[i], bL, acc[i][j]);
                wmma::mma_sync(acc[i][j], aL[i], bH, acc[i][j]);
            }
        }
    }

#pragma unroll
    for (int i = 0; i < 4; i++)
#pragma unroll
        for (int j = 0; j < 2; j++) {
            float* cp = &C[(size_t)(bm + wm + i * 16) * HD + bn + wn + j * 16];
            wmma::store_matrix_sync(cp, acc[i][j], HD, wmma::mem_row_major);
        }
}

// ------------------------------------------------ el/er per (node, head, p)
__global__ void eler_kernel(const float* __restrict__ al,
                            const float* __restrict__ ar) {
    int p = blockIdx.y;
    int n = blockIdx.x;
    int h = threadIdx.x >> 5;
    int lane = threadIdx.x & 31;
    float2 f = *(const float2*)&d_feat[p][(size_t)n * HD + h * HIDD + lane * 2];
    float2 a = *(const float2*)&al[p * HD + h * HIDD + lane * 2];
    float2 b = *(const float2*)&ar[p * HD + h * HIDD + lane * 2];
    float sl = f.x * a.x + f.y * a.y;
    float sr = f.x * b.x + f.y * b.y;
#pragma unroll
    for (int o = 16; o; o >>= 1) {
        sl += __shfl_xor_sync(0xffffffffu, sl, o);
        sr += __shfl_xor_sync(0xffffffffu, sr, o);
    }
    if (lane == 0) {
        d_el[p][n * N_HEADS + h] = sl;
        d_er[p][n * N_HEADS + h] = sr;
    }
}

// ------------------------------------------------ CSR build by dst
__global__ void hist_kernel(const int* __restrict__ dst) {
    int p = blockIdx.y;
    int e = blockIdx.x * blockDim.x + threadIdx.x;
    if (e < NE) atomicAdd(&d_counts[p][dst[p * NE + e]], 1);
}

__global__ void scan_kernel() {
    int p = blockIdx.x;
    __shared__ int sh[1024];
    int t = threadIdx.x;
    int base = t * 8;
    int loc[8];
    int s = 0;
#pragma unroll
    for (int i = 0; i < 8; i++) { loc[i] = s; s += d_counts[p][base + i]; }
    sh[t] = s;
    __syncthreads();
    for (int ofs = 1; ofs < 1024; ofs <<= 1) {
        int v = (t >= ofs) ? sh[t - ofs] : 0;
        __syncthreads();
        sh[t] += v;
        __syncthreads();
    }
    int pre = (t == 0) ? 0 : sh[t - 1];
#pragma unroll
    for (int i = 0; i < 8; i++) {
        int o = pre + loc[i];
        d_offsets[p][base + i] = o;
        d_cursor[p][base + i] = o;
    }
    if (t == 1023) d_offsets[p][N_NODES] = sh[1023];
}

__global__ void csr_scatter_kernel(const int* __restrict__ src,
                                   const int* __restrict__ dst) {
    int p = blockIdx.y;
    int e = blockIdx.x * blockDim.x + threadIdx.x;
    if (e < NE) {
        int pos = atomicAdd(&d_cursor[p][dst[p * NE + e]], 1);
        d_csrsrc[p][pos] = src[p * NE + e];
    }
}

// ------------------------------------------------ single-pass softmax + aggregation
// one warp per (dst, head); unrolled x4 batched loads (R7 measured-best form)
__global__ void gat_aggregate_kernel(const float* __restrict__ bias) {
    int p = blockIdx.y;
    int dn = blockIdx.x;
    int h = threadIdx.x >> 5;
    int lane = threadIdx.x & 31;
    int s0 = d_offsets[p][dn], s1 = d_offsets[p][dn + 1];
    float erv = d_er[p][dn * N_HEADS + h];
    const float* __restrict__ el = d_el[p];
    const int* __restrict__ csrc = d_csrsrc[p];
    const float* fb = &d_feat[p][h * HIDD + lane * 2];

    float ssum = 0.f, accx = 0.f, accy = 0.f;

    int i = s0;
    for (; i + 4 <= s1; i += 4) {
        int s_0 = csrc[i + 0];
        int s_1 = csrc[i + 1];
        int s_2 = csrc[i + 2];
        int s_3 = csrc[i + 3];
        float e_0 = el[s_0 * N_HEADS + h];
        float e_1 = el[s_1 * N_HEADS + h];
        float e_2 = el[s_2 * N_HEADS + h];
        float e_3 = el[s_3 * N_HEADS + h];
        float2 f_0 = *(const float2*)(fb + (size_t)s_0 * HD);
        float2 f_1 = *(const float2*)(fb + (size_t)s_1 * HD);
        float2 f_2 = *(const float2*)(fb + (size_t)s_2 * HD);
        float2 f_3 = *(const float2*)(fb + (size_t)s_3 * HD);

        float v0 = e_0 + erv; v0 = v0 > 0.f ? v0 : 0.2f * v0;
        float v1 = e_1 + erv; v1 = v1 > 0.f ? v1 : 0.2f * v1;
        float v2 = e_2 + erv; v2 = v2 > 0.f ? v2 : 0.2f * v2;
        float v3 = e_3 + erv; v3 = v3 > 0.f ? v3 : 0.2f * v3;
        float a0 = __expf(v0), a1 = __expf(v1), a2 = __expf(v2), a3 = __expf(v3);
        ssum += (a0 + a1) + (a2 + a3);
        accx += a0 * f_0.x + a1 * f_1.x + a2 * f_2.x + a3 * f_3.x;
        accy += a0 * f_0.y + a1 * f_1.y + a2 * f_2.y + a3 * f_3.y;
    }
    for (; i < s1; i++) {
        int s = csrc[i];
        float ev = el[s * N_HEADS + h] + erv;
        ev = ev > 0.f ? ev : 0.2f * ev;
        float a = __expf(ev);
        float2 f = *(const float2*)(fb + (size_t)s * HD);
        ssum += a;
        accx += a * f.x;
        accy += a * f.y;
    }

    float inv = ssum > 0.f ? 1.f / ssum : 0.f;
    if (lane == 0) d_invd[p][dn * N_HEADS + h] = inv;

    float bx = bias[p * HD + h * HIDD + lane * 2];
    float by = bias[p * HD + h * HIDD + lane * 2 + 1];
    float ox = accx * inv + bx, oy = accy * inv + by;
    ox = ox > 0.f ? ox : (__expf(ox) - 1.f);
    oy = oy > 0.f ? oy : (__expf(oy) - 1.f);
    *(float2*)&d_zp[p][(size_t)dn * HD + h * HIDD + lane * 2] = make_float2(ox, oy);
}

// ------------------------------------------------ semantic attention
__global__ void sem_v_kernel(const float* __restrict__ w1,
                             const float* __restrict__ w2,
                             const float* __restrict__ b1) {
    int k = threadIdx.x + blockIdx.x * blockDim.x;
    float s = 0.f;
    for (int j = 0; j < 128; j++) s += w1[k * 128 + j] * w2[j];
    d_v[k] = s;
    if (k == 0) {
        float c = 0.f;
        for (int j = 0; j < 128; j++) c += b1[j] * w2[j];
        d_c = c;
    }
}

__global__ void sem_w_kernel() {
    int gw = (blockIdx.x * blockDim.x + threadIdx.x) >> 5;
    int lane = threadIdx.x & 31;
    int n = gw / P_META;
    int p = gw - n * P_META;
    if (n >= N_NODES) return;
    const float* z = &d_zp[p][(size_t)n * HD];
    float s = 0.f;
#pragma unroll
    for (int k = lane; k < HD; k += 32) s += z[k] * d_v[k];
#pragma unroll
    for (int o = 16; o; o >>= 1) s += __shfl_xor_sync(0xffffffffu, s, o);
    if (lane == 0) {
        float w = s + d_c;
        w = w > 0.f ? w : 0.01f * w;
        atomicAdd(&d_wsum[p], w);
    }
}

__global__ void beta_kernel() {
    if (threadIdx.x == 0) {
        float w0 = d_wsum[0] / (float)N_NODES;
        float w1 = d_wsum[1] / (float)N_NODES;
        float w2 = d_wsum[2] / (float)N_NODES;
        float mx = fmaxf(w0, fmaxf(w1, w2));
        float e0 = expf(w0 - mx), e1 = expf(w1 - mx), e2 = expf(w2 - mx);
        float s = e0 + e1 + e2;
        d_beta[0] = e0 / s;
        d_beta[1] = e1 / s;
        d_beta[2] = e2 / s;
    }
}

// ------------------------------------------------ z = sum_p beta_p * zp
__global__ void combine_z_kernel() {
    int i = blockIdx.x * blockDim.x + threadIdx.x;
    float b0 = d_beta[0], b1 = d_beta[1], b2 = d_beta[2];
    float4 a = ((const float4*)&d_zp[0][0])[i];
    float4 b = ((const float4*)&d_zp[1][0])[i];
    float4 c = ((const float4*)&d_zp[2][0])[i];
    float4 r;
    r.x = b0 * a.x + b1 * b.x + b2 * c.x;
    r.y = b0 * a.y + b1 * b.y + b2 * c.y;
    r.z = b0 * a.z + b1 * b.z + b2 * c.z;
    r.w = b0 * a.w + b1 * b.w + b2 * c.w;
    ((float4*)d_z)[i] = r;
}

// ------------------------------------------------ out = z @ pred_w + pred_b
__global__ void out_kernel(const float* __restrict__ pw,
                           const float* __restrict__ pb,
                           float* __restrict__ out) {
    __shared__ float zs[HD];
    int n = blockIdx.x;
    int t = threadIdx.x;
    for (int k = t; k < HD; k += 64) zs[k] = d_z[(size_t)n * HD + k];
    __syncthreads();
    float acc = pb[t];
#pragma unroll 8
    for (int k = 0; k < HD; k++) acc += zs[k] * pw[k * OUT_F + t];
    out[(size_t)n * OUT_F + t] = acc;
}

// ------------------------------------------------ atten scatter (fused alpha)
__global__ void atten_scatter_kernel(const int* __restrict__ src,
                                     const int* __restrict__ dst,
                                     float* __restrict__ atten) {
    int p = blockIdx.y;
    int e = blockIdx.x * blockDim.x + threadIdx.x;
    if (e >= NE) return;
    int s = src[p * NE + e];
    int d = dst[p * NE + e];
    const float* elrow = &d_el[p][s * N_HEADS];
    const float* errow = &d_er[p][d * N_HEADS];
    const float* invrow = &d_invd[p][d * N_HEADS];
    float a = 0.f;
#pragma unroll
    for (int h = 0; h < N_HEADS; h++) {
        float ev = elrow[h] + errow[h];
        ev = ev > 0.f ? ev : 0.2f * ev;
        a += __expf(ev) * invrow[h];
    }
    float v = a * 0.125f * d_beta[p];
    atomicAdd(&atten[(size_t)s * N_NODES + d], v);
}

// ---------------------------------------------------------------- launcher
extern "C" void kernel_launch(void* const* d_in, const int* in_sizes, int n_in,
                              void* d_out, int out_size) {
    const float* h    = (const float*)d_in[0];
    const int*   esrc = (const int*)d_in[1];
    const int*   edst = (const int*)d_in[2];
    const float* fc   = (const float*)d_in[3];
    const float* al   = (const float*)d_in[4];
    const float* ar   = (const float*)d_in[5];
    const float* bias = (const float*)d_in[6];
    const float* w1   = (const float*)d_in[7];
    const float* b1   = (const float*)d_in[8];
    const float* w2   = (const float*)d_in[9];
    const float* pw   = (const float*)d_in[10];
    const float* pb   = (const float*)d_in[11];

    const long long SZ_OUT   = (long long)N_NODES * OUT_F;
    const long long SZ_ATTEN = (long long)N_NODES * N_NODES;
    long long osz = (long long)out_size;

    float* out_ptr = nullptr;
    float* atten_ptr = nullptr;
    if (osz >= SZ_OUT + SZ_ATTEN) {
        out_ptr = (float*)d_out;
        atten_ptr = out_ptr + SZ_OUT;
    } else if (osz == SZ_OUT) {
        out_ptr = (float*)d_out;
    } else if (osz == SZ_ATTEN) {
        atten_ptr = (float*)d_out;
    } else {
        out_ptr = (float*)d_out;
    }

    // ---- two side streams: CSR chain, atten zero-fill (static one-time init)
    static cudaStream_t sA = (cudaStream_t)0, sB = (cudaStream_t)0;
    static cudaEvent_t evFork = nullptr, evA = nullptr, evB = nullptr;
    static int streams_ok = -1;
    if (streams_ok < 0) {
        cudaStream_t t1, t2;
        cudaEvent_t e0, e1, e2;
        if (cudaStreamCreateWithFlags(&t1, cudaStreamNonBlocking) == cudaSuccess &&
            cudaStreamCreateWithFlags(&t2, cudaStreamNonBlocking) == cudaSuccess &&
            cudaEventCreateWithFlags(&e0, cudaEventDisableTiming) == cudaSuccess &&
            cudaEventCreateWithFlags(&e1, cudaEventDisableTiming) == cudaSuccess &&
            cudaEventCreateWithFlags(&e2, cudaEventDisableTiming) == cudaSuccess) {
            sA = t1; sB = t2; evFork = e0; evA = e1; evB = e2; streams_ok = 1;
        } else {
            streams_ok = 0;
        }
    }
    cudaStream_t strA = streams_ok ? sA : (cudaStream_t)0;
    cudaStream_t strB = streams_ok ? sB : (cudaStream_t)0;

    if (streams_ok) {
        cudaEventRecord(evFork, (cudaStream_t)0);
        cudaStreamWaitEvent(strA, evFork, 0);
        cudaStreamWaitEvent(strB, evFork, 0);
    }

    // stream A: CSR build chain (needed before aggregate)
    zero_misc_kernel<<<dim3(N_NODES / 256, P_META), 256, 0, strA>>>();
    hist_kernel<<<dim3(NE / 256, P_META), 256, 0, strA>>>(edst);
    scan_kernel<<<P_META, 1024, 0, strA>>>();
    csr_scatter_kernel<<<dim3(NE / 256, P_META), 256, 0, strA>>>(esrc, edst);

    // stream B: atten zero-fill (needed only before atten_scatter)
    if (atten_ptr)
        zero_atten_kernel<<<(N_NODES * (N_NODES / 4)) / 256, 256, 0, strB>>>(
            (float4*)atten_ptr);

    // main: tensor-core GEMM + el/er
    gemm_feat_tf32_kernel<<<dim3(HD / 128, N_NODES / 128, P_META), 256>>>(h, fc);
    eler_kernel<<<dim3(N_NODES, P_META), 256>>>(al, ar);

    if (streams_ok) {
        cudaEventRecord(evA, strA);
        cudaStreamWaitEvent((cudaStream_t)0, evA, 0);
    }

    gat_aggregate_kernel<<<dim3(N_NODES, P_META), 256>>>(bias);

    sem_v_kernel<<<2, 256>>>(w1, w2, b1);
    sem_w_kernel<<<(N_NODES * P_META * 32) / 256, 256>>>();
    beta_kernel<<<1, 32>>>();
    combine_z_kernel<<<(N_NODES * HD / 4) / 256, 256>>>();
    if (out_ptr)
        out_kernel<<<N_NODES, 64>>>(pw, pb, out_ptr);
    if (atten_ptr) {
        if (streams_ok) {
            cudaEventRecord(evB, strB);
            cudaStreamWaitEvent((cudaStream_t)0, evB, 0);
        }
        atten_scatter_kernel<<<dim3(NE / 256, P_META), 256>>>(esrc, edst, atten_ptr);
    }
}

// round 10
// speedup vs baseline: 1.3514x; 1.3514x over previous
#include <cuda_runtime.h>
#include <cuda_fp16.h>
#include <math.h>

#define N_NODES 8192
#define P_META 3
#define IN_F 256
#define HIDD 64
#define N_HEADS 8
#define HD 512
#define OUT_F 64
#define NE 262144

// ---------------- scratch (static device allocations; no runtime alloc) ----
__device__ float  d_feat[P_META][N_NODES * HD];     // 48 MB (fp32, for eler)
__device__ __half d_feat16[P_META][N_NODES * HD];   // 24 MB (fp16, for gathers)
__device__ float  d_zp[P_META][N_NODES * HD];       // 48 MB
__device__ float  d_el[P_META][N_NODES * N_HEADS];
__device__ float  d_er[P_META][N_NODES * N_HEADS];
__device__ float  d_invd[P_META][N_NODES * N_HEADS];
__device__ int    d_counts[P_META][N_NODES];
__device__ int    d_cursor[P_META][N_NODES];
__device__ int    d_offsets[P_META][N_NODES + 1];
__device__ int    d_csrsrc[P_META][NE];
__device__ float  d_wsum[P_META];
__device__ float  d_beta[P_META];
__device__ float  d_v[HD];
__device__ float  d_c;
__device__ float  d_z[N_NODES * HD];

// ---------------------------------------------------------------- utilities
__global__ void zero_misc_kernel() {
    int p = blockIdx.y;
    int i = blockIdx.x * blockDim.x + threadIdx.x;
    if (i < N_NODES) d_counts[p][i] = 0;
    if (p == 0 && i < P_META) d_wsum[i] = 0.f;
}

__global__ void zero_atten_kernel(float4* a) {
    int i = blockIdx.x * blockDim.x + threadIdx.x;
    a[i] = make_float4(0.f, 0.f, 0.f, 0.f);
}

// ------------------------------------------------ feat = h @ fc_p (fp32 GEMM)
// R4/R7 measured-best FFMA GEMM (at the 3-reg FFMA issue roofline), plus an
// epilogue-local fp16 mirror write (no live registers across the main loop).
__global__ void __launch_bounds__(256, 2)
gemm_feat_kernel(const float* __restrict__ A,    // [8192,256]
                 const float* __restrict__ fc) { // [P,256,512]
    const int p = blockIdx.z;
    const float* __restrict__ B = fc + (size_t)p * IN_F * HD;
    float* __restrict__ C = d_feat[p];
    __half* __restrict__ C16 = d_feat16[p];
    __shared__ float As[8][128];
    __shared__ float Bs[8][128];
    const int bm = blockIdx.y * 128;
    const int bn = blockIdx.x * 128;
    const int t = threadIdx.x;
    const int ty = t >> 4, tx = t & 15;

    const int arow = t >> 1;
    const int acol = (t & 1) * 4;
    const int brow = t >> 5;
    const int bcol = (t & 31) * 4;

    float acc[8][8];
#pragma unroll
    for (int i = 0; i < 8; i++)
#pragma unroll
        for (int j = 0; j < 8; j++) acc[i][j] = 0.f;

    for (int k0 = 0; k0 < IN_F; k0 += 8) {
        float4 av = *(const float4*)&A[(size_t)(bm + arow) * IN_F + k0 + acol];
        float4 bv = *(const float4*)&B[(size_t)(k0 + brow) * HD + bn + bcol];
        __syncthreads();
        As[acol + 0][arow] = av.x;
        As[acol + 1][arow] = av.y;
        As[acol + 2][arow] = av.z;
        As[acol + 3][arow] = av.w;
        *(float4*)&Bs[brow][bcol] = bv;
        __syncthreads();
#pragma unroll
        for (int k = 0; k < 8; k++) {
            float a[8], b[8];
            *(float4*)&a[0] = *(const float4*)&As[k][ty * 8];
            *(float4*)&a[4] = *(const float4*)&As[k][ty * 8 + 4];
            *(float4*)&b[0] = *(const float4*)&Bs[k][tx * 8];
            *(float4*)&b[4] = *(const float4*)&Bs[k][tx * 8 + 4];
#pragma unroll
            for (int i = 0; i < 8; i++)
#pragma unroll
                for (int j = 0; j < 8; j++) acc[i][j] += a[i] * b[j];
        }
    }
#pragma unroll
    for (int i = 0; i < 8; i++) {
        size_t roff = (size_t)(bm + ty * 8 + i) * HD + bn + tx * 8;
        float* cr = &C[roff];
        *(float4*)&cr[0] = make_float4(acc[i][0], acc[i][1], acc[i][2], acc[i][3]);
        *(float4*)&cr[4] = make_float4(acc[i][4], acc[i][5], acc[i][6], acc[i][7]);
        __half2* hr = (__half2*)&C16[roff];
        hr[0] = __floats2half2_rn(acc[i][0], acc[i][1]);
        hr[1] = __floats2half2_rn(acc[i][2], acc[i][3]);
        hr[2] = __floats2half2_rn(acc[i][4], acc[i][5]);
        hr[3] = __floats2half2_rn(acc[i][6], acc[i][7]);
    }
}

// ------------------------------------------------ el/er per (node, head, p)
__global__ void eler_kernel(const float* __restrict__ al,
                            const float* __restrict__ ar) {
    int p = blockIdx.y;
    int n = blockIdx.x;
    int h = threadIdx.x >> 5;
    int lane = threadIdx.x & 31;
    float2 f = *(const float2*)&d_feat[p][(size_t)n * HD + h * HIDD + lane * 2];
    float2 a = *(const float2*)&al[p * HD + h * HIDD + lane * 2];
    float2 b = *(const float2*)&ar[p * HD + h * HIDD + lane * 2];
    float sl = f.x * a.x + f.y * a.y;
    float sr = f.x * b.x + f.y * b.y;
#pragma unroll
    for (int o = 16; o; o >>= 1) {
        sl += __shfl_xor_sync(0xffffffffu, sl, o);
        sr += __shfl_xor_sync(0xffffffffu, sr, o);
    }
    if (lane == 0) {
        d_el[p][n * N_HEADS + h] = sl;
        d_er[p][n * N_HEADS + h] = sr;
    }
}

// ------------------------------------------------ CSR build by dst
__global__ void hist_kernel(const int* __restrict__ dst) {
    int p = blockIdx.y;
    int e = blockIdx.x * blockDim.x + threadIdx.x;
    if (e < NE) atomicAdd(&d_counts[p][dst[p * NE + e]], 1);
}

__global__ void scan_kernel() {
    int p = blockIdx.x;
    __shared__ int sh[1024];
    int t = threadIdx.x;
    int base = t * 8;
    int loc[8];
    int s = 0;
#pragma unroll
    for (int i = 0; i < 8; i++) { loc[i] = s; s += d_counts[p][base + i]; }
    sh[t] = s;
    __syncthreads();
    for (int ofs = 1; ofs < 1024; ofs <<= 1) {
        int v = (t >= ofs) ? sh[t - ofs] : 0;
        __syncthreads();
        sh[t] += v;
        __syncthreads();
    }
    int pre = (t == 0) ? 0 : sh[t - 1];
#pragma unroll
    for (int i = 0; i < 8; i++) {
        int o = pre + loc[i];
        d_offsets[p][base + i] = o;
        d_cursor[p][base + i] = o;
    }
    if (t == 1023) d_offsets[p][N_NODES] = sh[1023];
}

__global__ void csr_scatter_kernel(const int* __restrict__ src,
                                   const int* __restrict__ dst) {
    int p = blockIdx.y;
    int e = blockIdx.x * blockDim.x + threadIdx.x;
    if (e < NE) {
        int pos = atomicAdd(&d_cursor[p][dst[p * NE + e]], 1);
        d_csrsrc[p][pos] = src[p * NE + e];
    }
}

// ------------------------------------------------ single-pass softmax + aggregation
// one warp per (dst, head); unrolled x4 batched loads; feature gather in fp16
// (halves the dominant L2 traffic; weights and el/er stay fp32).
__global__ void gat_aggregate_kernel(const float* __restrict__ bias) {
    int p = blockIdx.y;
    int dn = blockIdx.x;
    int h = threadIdx.x >> 5;
    int lane = threadIdx.x & 31;
    int s0 = d_offsets[p][dn], s1 = d_offsets[p][dn + 1];
    float erv = d_er[p][dn * N_HEADS + h];
    const float* __restrict__ el = d_el[p];
    const int* __restrict__ csrc = d_csrsrc[p];
    const __half* fb = &d_feat16[p][h * HIDD + lane * 2];

    float ssum = 0.f, accx = 0.f, accy = 0.f;

    int i = s0;
    for (; i + 4 <= s1; i += 4) {
        int s_0 = csrc[i + 0];
        int s_1 = csrc[i + 1];
        int s_2 = csrc[i + 2];
        int s_3 = csrc[i + 3];
        float e_0 = el[s_0 * N_HEADS + h];
        float e_1 = el[s_1 * N_HEADS + h];
        float e_2 = el[s_2 * N_HEADS + h];
        float e_3 = el[s_3 * N_HEADS + h];
        float2 f_0 = __half22float2(*(const __half2*)(fb + (size_t)s_0 * HD));
        float2 f_1 = __half22float2(*(const __half2*)(fb + (size_t)s_1 * HD));
        float2 f_2 = __half22float2(*(const __half2*)(fb + (size_t)s_2 * HD));
        float2 f_3 = __half22float2(*(const __half2*)(fb + (size_t)s_3 * HD));

        float v0 = e_0 + erv; v0 = v0 > 0.f ? v0 : 0.2f * v0;
        float v1 = e_1 + erv; v1 = v1 > 0.f ? v1 : 0.2f * v1;
        float v2 = e_2 + erv; v2 = v2 > 0.f ? v2 : 0.2f * v2;
        float v3 = e_3 + erv; v3 = v3 > 0.f ? v3 : 0.2f * v3;
        float a0 = __expf(v0), a1 = __expf(v1), a2 = __expf(v2), a3 = __expf(v3);
        ssum += (a0 + a1) + (a2 + a3);
        accx += a0 * f_0.x + a1 * f_1.x + a2 * f_2.x + a3 * f_3.x;
        accy += a0 * f_0.y + a1 * f_1.y + a2 * f_2.y + a3 * f_3.y;
    }
    for (; i < s1; i++) {
        int s = csrc[i];
        float ev = el[s * N_HEADS + h] + erv;
        ev = ev > 0.f ? ev : 0.2f * ev;
        float a = __expf(ev);
        float2 f = __half22float2(*(const __half2*)(fb + (size_t)s * HD));
        ssum += a;
        accx += a * f.x;
        accy += a * f.y;
    }

    float inv = ssum > 0.f ? 1.f / ssum : 0.f;
    if (lane == 0) d_invd[p][dn * N_HEADS + h] = inv;

    float bx = bias[p * HD + h * HIDD + lane * 2];
    float by = bias[p * HD + h * HIDD + lane * 2 + 1];
    float ox = accx * inv + bx, oy = accy * inv + by;
    ox = ox > 0.f ? ox : (__expf(ox) - 1.f);
    oy = oy > 0.f ? oy : (__expf(oy) - 1.f);
    *(float2*)&d_zp[p][(size_t)dn * HD + h * HIDD + lane * 2] = make_float2(ox, oy);
}

// ------------------------------------------------ semantic attention
__global__ void sem_v_kernel(const float* __restrict__ w1,
                             const float* __restrict__ w2,
                             const float* __restrict__ b1) {
    int k = threadIdx.x + blockIdx.x * blockDim.x;
    float s = 0.f;
    for (int j = 0; j < 128; j++) s += w1[k * 128 + j] * w2[j];
    d_v[k] = s;
    if (k == 0) {
        float c = 0.f;
        for (int j = 0; j < 128; j++) c += b1[j] * w2[j];
        d_c = c;
    }
}

__global__ void sem_w_kernel() {
    int gw = (blockIdx.x * blockDim.x + threadIdx.x) >> 5;
    int lane = threadIdx.x & 31;
    int n = gw / P_META;
    int p = gw - n * P_META;
    if (n >= N_NODES) return;
    const float* z = &d_zp[p][(size_t)n * HD];
    float s = 0.f;
#pragma unroll
    for (int k = lane; k < HD; k += 32) s += z[k] * d_v[k];
#pragma unroll
    for (int o = 16; o; o >>= 1) s += __shfl_xor_sync(0xffffffffu, s, o);
    if (lane == 0) {
        float w = s + d_c;
        w = w > 0.f ? w : 0.01f * w;
        atomicAdd(&d_wsum[p], w);
    }
}

__global__ void beta_kernel() {
    if (threadIdx.x == 0) {
        float w0 = d_wsum[0] / (float)N_NODES;
        float w1 = d_wsum[1] / (float)N_NODES;
        float w2 = d_wsum[2] / (float)N_NODES;
        float mx = fmaxf(w0, fmaxf(w1, w2));
        float e0 = expf(w0 - mx), e1 = expf(w1 - mx), e2 = expf(w2 - mx);
        float s = e0 + e1 + e2;
        d_beta[0] = e0 / s;
        d_beta[1] = e1 / s;
        d_beta[2] = e2 / s;
    }
}

// ------------------------------------------------ z = sum_p beta_p * zp
__global__ void combine_z_kernel() {
    int i = blockIdx.x * blockDim.x + threadIdx.x;
    float b0 = d_beta[0], b1 = d_beta[1], b2 = d_beta[2];
    float4 a = ((const float4*)&d_zp[0][0])[i];
    float4 b = ((const float4*)&d_zp[1][0])[i];
    float4 c = ((const float4*)&d_zp[2][0])[i];
    float4 r;
    r.x = b0 * a.x + b1 * b.x + b2 * c.x;
    r.y = b0 * a.y + b1 * b.y + b2 * c.y;
    r.z = b0 * a.z + b1 * b.z + b2 * c.z;
    r.w = b0 * a.w + b1 * b.w + b2 * c.w;
    ((float4*)d_z)[i] = r;
}

// ------------------------------------------------ out = z @ pred_w + pred_b
__global__ void out_kernel(const float* __restrict__ pw,
                           const float* __restrict__ pb,
                           float* __restrict__ out) {
    __shared__ float zs[HD];
    int n = blockIdx.x;
    int t = threadIdx.x;
    for (int k = t; k < HD; k += 64) zs[k] = d_z[(size_t)n * HD + k];
    __syncthreads();
    float acc = pb[t];
#pragma unroll 8
    for (int k = 0; k < HD; k++) acc += zs[k] * pw[k * OUT_F + t];
    out[(size_t)n * OUT_F + t] = acc;
}

// ------------------------------------------------ atten scatter (fused alpha)
__global__ void atten_scatter_kernel(const int* __restrict__ src,
                                     const int* __restrict__ dst,
                                     float* __restrict__ atten) {
    int p = blockIdx.y;
    int e = blockIdx.x * blockDim.x + threadIdx.x;
    if (e >= NE) return;
    int s = src[p * NE + e];
    int d = dst[p * NE + e];
    const float* elrow = &d_el[p][s * N_HEADS];
    const float* errow = &d_er[p][d * N_HEADS];
    const float* invrow = &d_invd[p][d * N_HEADS];
    float a = 0.f;
#pragma unroll
    for (int h = 0; h < N_HEADS; h++) {
        float ev = elrow[h] + errow[h];
        ev = ev > 0.f ? ev : 0.2f * ev;
        a += __expf(ev) * invrow[h];
    }
    float v = a * 0.125f * d_beta[p];
    atomicAdd(&atten[(size_t)s * N_NODES + d], v);
}

// ---------------------------------------------------------------- launcher
extern "C" void kernel_launch(void* const* d_in, const int* in_sizes, int n_in,
                              void* d_out, int out_size) {
    const float* h    = (const float*)d_in[0];
    const int*   esrc = (const int*)d_in[1];
    const int*   edst = (const int*)d_in[2];
    const float* fc   = (const float*)d_in[3];
    const float* al   = (const float*)d_in[4];
    const float* ar   = (const float*)d_in[5];
    const float* bias = (const float*)d_in[6];
    const float* w1   = (const float*)d_in[7];
    const float* b1   = (const float*)d_in[8];
    const float* w2   = (const float*)d_in[9];
    const float* pw   = (const float*)d_in[10];
    const float* pb   = (const float*)d_in[11];

    const long long SZ_OUT   = (long long)N_NODES * OUT_F;
    const long long SZ_ATTEN = (long long)N_NODES * N_NODES;
    long long osz = (long long)out_size;

    float* out_ptr = nullptr;
    float* atten_ptr = nullptr;
    if (osz >= SZ_OUT + SZ_ATTEN) {
        out_ptr = (float*)d_out;
        atten_ptr = out_ptr + SZ_OUT;
    } else if (osz == SZ_OUT) {
        out_ptr = (float*)d_out;
    } else if (osz == SZ_ATTEN) {
        atten_ptr = (float*)d_out;
    } else {
        out_ptr = (float*)d_out;
    }

    // ---- two side streams: CSR chain, atten zero-fill (static one-time init)
    static cudaStream_t sA = (cudaStream_t)0, sB = (cudaStream_t)0;
    static cudaEvent_t evFork = nullptr, evA = nullptr, evB = nullptr;
    static int streams_ok = -1;
    if (streams_ok < 0) {
        cudaStream_t t1, t2;
        cudaEvent_t e0, e1, e2;
        if (cudaStreamCreateWithFlags(&t1, cudaStreamNonBlocking) == cudaSuccess &&
            cudaStreamCreateWithFlags(&t2, cudaStreamNonBlocking) == cudaSuccess &&
            cudaEventCreateWithFlags(&e0, cudaEventDisableTiming) == cudaSuccess &&
            cudaEventCreateWithFlags(&e1, cudaEventDisableTiming) == cudaSuccess &&
            cudaEventCreateWithFlags(&e2, cudaEventDisableTiming) == cudaSuccess) {
            sA = t1; sB = t2; evFork = e0; evA = e1; evB = e2; streams_ok = 1;
        } else {
            streams_ok = 0;
        }
    }
    cudaStream_t strA = streams_ok ? sA : (cudaStream_t)0;
    cudaStream_t strB = streams_ok ? sB : (cudaStream_t)0;

    if (streams_ok) {
        cudaEventRecord(evFork, (cudaStream_t)0);
        cudaStreamWaitEvent(strA, evFork, 0);
        cudaStreamWaitEvent(strB, evFork, 0);
    }

    // stream A: CSR build chain (needed before aggregate)
    zero_misc_kernel<<<dim3(N_NODES / 256, P_META), 256, 0, strA>>>();
    hist_kernel<<<dim3(NE / 256, P_META), 256, 0, strA>>>(edst);
    scan_kernel<<<P_META, 1024, 0, strA>>>();
    csr_scatter_kernel<<<dim3(NE / 256, P_META), 256, 0, strA>>>(esrc, edst);

    // stream B: atten zero-fill (needed only before atten_scatter)
    if (atten_ptr)
        zero_atten_kernel<<<(N_NODES * (N_NODES / 4)) / 256, 256, 0, strB>>>(
            (float4*)atten_ptr);

    // main: FFMA GEMM (+fp16 mirror) + el/er
    gemm_feat_kernel<<<dim3(HD / 128, N_NODES / 128, P_META), 256>>>(h, fc);
    eler_kernel<<<dim3(N_NODES, P_META), 256>>>(al, ar);

    if (streams_ok) {
        cudaEventRecord(evA, strA);
        cudaStreamWaitEvent((cudaStream_t)0, evA, 0);
    }

    gat_aggregate_kernel<<<dim3(N_NODES, P_META), 256>>>(bias);

    sem_v_kernel<<<2, 256>>>(w1, w2, b1);
    sem_w_kernel<<<(N_NODES * P_META * 32) / 256, 256>>>();
    beta_kernel<<<1, 32>>>();
    combine_z_kernel<<<(N_NODES * HD / 4) / 256, 256>>>();
    if (out_ptr)
        out_kernel<<<N_NODES, 64>>>(pw, pb, out_ptr);
    if (atten_ptr) {
        if (streams_ok) {
            cudaEventRecord(evB, strB);
            cudaStreamWaitEvent((cudaStream_t)0, evB, 0);
        }
        atten_scatter_kernel<<<dim3(NE / 256, P_META), 256>>>(esrc, edst, atten_ptr);
    }
}

// round 13
// speedup vs baseline: 1.4292x; 1.0576x over previous
#include <cuda_runtime.h>
#include <cuda_fp16.h>
#include <math.h>

#define N_NODES 8192
#define P_META 3
#define IN_F 256
#define HIDD 64
#define N_HEADS 8
#define HD 512
#define OUT_F 64
#define NE 262144

// ---------------- scratch (static device allocations) ----------------
__device__ __half d_feat16[P_META][N_NODES * HD];   // 24 MB (sole feat copy)
__device__ float  d_zp[P_META][N_NODES * HD];       // 48 MB
__device__ float  d_el[P_META][N_NODES * N_HEADS];
__device__ float  d_er[P_META][N_NODES * N_HEADS];
__device__ float  d_invd[P_META][N_NODES * N_HEADS];
__device__ int    d_counts[P_META][N_NODES];
__device__ int    d_cursor[P_META][N_NODES];
__device__ int    d_offsets[P_META][N_NODES + 1];
__device__ int    d_csrsrc[P_META][NE];
__device__ float  d_wsum[P_META];
__device__ float  d_beta[P_META];
__device__ float  d_v[HD];
__device__ float  d_c;

// ---------------------------------------------------------------- utilities
__global__ void zero_misc_kernel() {
    int p = blockIdx.y;
    int i = blockIdx.x * blockDim.x + threadIdx.x;
    if (i < N_NODES) d_counts[p][i] = 0;
    if (p == 0 && i < P_META) d_wsum[i] = 0.f;
}

__global__ void zero_atten_kernel(float4* a) {
    int i = blockIdx.x * blockDim.x + threadIdx.x;
    a[i] = make_float4(0.f, 0.f, 0.f, 0.f);
}

// ------------------------------------------------ feat = h @ fc_p (fp32 GEMM)
// Measured-best FFMA GEMM; epilogue writes ONLY the fp16 mirror.
__global__ void __launch_bounds__(256, 2)
gemm_feat_kernel(const float* __restrict__ A,    // [8192,256]
                 const float* __restrict__ fc) { // [P,256,512]
    const int p = blockIdx.z;
    const float* __restrict__ B = fc + (size_t)p * IN_F * HD;
    __half* __restrict__ C16 = d_feat16[p];
    __shared__ float As[8][128];
    __shared__ float Bs[8][128];
    const int bm = blockIdx.y * 128;
    const int bn = blockIdx.x * 128;
    const int t = threadIdx.x;
    const int ty = t >> 4, tx = t & 15;

    const int arow = t >> 1;
    const int acol = (t & 1) * 4;
    const int brow = t >> 5;
    const int bcol = (t & 31) * 4;

    float acc[8][8];
#pragma unroll
    for (int i = 0; i < 8; i++)
#pragma unroll
        for (int j = 0; j < 8; j++) acc[i][j] = 0.f;

    for (int k0 = 0; k0 < IN_F; k0 += 8) {
        float4 av = *(const float4*)&A[(size_t)(bm + arow) * IN_F + k0 + acol];
        float4 bv = *(const float4*)&B[(size_t)(k0 + brow) * HD + bn + bcol];
        __syncthreads();
        As[acol + 0][arow] = av.x;
        As[acol + 1][arow] = av.y;
        As[acol + 2][arow] = av.z;
        As[acol + 3][arow] = av.w;
        *(float4*)&Bs[brow][bcol] = bv;
        __syncthreads();
#pragma unroll
        for (int k = 0; k < 8; k++) {
            float a[8], b[8];
            *(float4*)&a[0] = *(const float4*)&As[k][ty * 8];
            *(float4*)&a[4] = *(const float4*)&As[k][ty * 8 + 4];
            *(float4*)&b[0] = *(const float4*)&Bs[k][tx * 8];
            *(float4*)&b[4] = *(const float4*)&Bs[k][tx * 8 + 4];
#pragma unroll
            for (int i = 0; i < 8; i++)
#pragma unroll
                for (int j = 0; j < 8; j++) acc[i][j] += a[i] * b[j];
        }
    }
#pragma unroll
    for (int i = 0; i < 8; i++) {
        size_t roff = (size_t)(bm + ty * 8 + i) * HD + bn + tx * 8;
        __half2* hr = (__half2*)&C16[roff];
        hr[0] = __floats2half2_rn(acc[i][0], acc[i][1]);
        hr[1] = __floats2half2_rn(acc[i][2], acc[i][3]);
        hr[2] = __floats2half2_rn(acc[i][4], acc[i][5]);
        hr[3] = __floats2half2_rn(acc[i][6], acc[i][7]);
    }
}

// ------------------------------------------------ el/er per (node, head, p)
__global__ void eler_kernel(const float* __restrict__ al,
                            const float* __restrict__ ar) {
    int p = blockIdx.y;
    int n = blockIdx.x;
    int h = threadIdx.x >> 5;
    int lane = threadIdx.x & 31;
    float2 f = __half22float2(
        *(const __half2*)&d_feat16[p][(size_t)n * HD + h * HIDD + lane * 2]);
    float2 a = *(const float2*)&al[p * HD + h * HIDD + lane * 2];
    float2 b = *(const float2*)&ar[p * HD + h * HIDD + lane * 2];
    float sl = f.x * a.x + f.y * a.y;
    float sr = f.x * b.x + f.y * b.y;
#pragma unroll
    for (int o = 16; o; o >>= 1) {
        sl += __shfl_xor_sync(0xffffffffu, sl, o);
        sr += __shfl_xor_sync(0xffffffffu, sr, o);
    }
    if (lane == 0) {
        d_el[p][n * N_HEADS + h] = sl;
        d_er[p][n * N_HEADS + h] = sr;
    }
}

// ------------------------------------------------ CSR build by dst
__global__ void hist_kernel(const int* __restrict__ dst) {
    int p = blockIdx.y;
    int e = blockIdx.x * blockDim.x + threadIdx.x;
    if (e < NE) atomicAdd(&d_counts[p][dst[p * NE + e]], 1);
}

__global__ void scan_kernel() {
    int p = blockIdx.x;
    __shared__ int sh[1024];
    int t = threadIdx.x;
    int base = t * 8;
    int loc[8];
    int s = 0;
#pragma unroll
    for (int i = 0; i < 8; i++) { loc[i] = s; s += d_counts[p][base + i]; }
    sh[t] = s;
    __syncthreads();
    for (int ofs = 1; ofs < 1024; ofs <<= 1) {
        int v = (t >= ofs) ? sh[t - ofs] : 0;
        __syncthreads();
        sh[t] += v;
        __syncthreads();
    }
    int pre = (t == 0) ? 0 : sh[t - 1];
#pragma unroll
    for (int i = 0; i < 8; i++) {
        int o = pre + loc[i];
        d_offsets[p][base + i] = o;
        d_cursor[p][base + i] = o;
    }
    if (t == 1023) d_offsets[p][N_NODES] = sh[1023];
}

__global__ void csr_scatter_kernel(const int* __restrict__ src,
                                   const int* __restrict__ dst) {
    int p = blockIdx.y;
    int e = blockIdx.x * blockDim.x + threadIdx.x;
    if (e < NE) {
        int pos = atomicAdd(&d_cursor[p][dst[p * NE + e]], 1);
        d_csrsrc[p][pos] = src[p * NE + e];
    }
}

// ------------------------------------------------ aggregation: one warp per
// (dst, head); single pass, unrolled x8 batched loads, fp16 feature gather.
__global__ void gat_aggregate_kernel(const float* __restrict__ bias) {
    int p = blockIdx.y;
    int dn = blockIdx.x;
    int h = threadIdx.x >> 5;
    int lane = threadIdx.x & 31;
    int s0 = d_offsets[p][dn], s1 = d_offsets[p][dn + 1];
    float erv = d_er[p][dn * N_HEADS + h];
    const float* __restrict__ el = d_el[p];
    const int* __restrict__ csrc = d_csrsrc[p];
    const __half* fb = &d_feat16[p][h * HIDD + lane * 2];

    float ssum = 0.f, accx = 0.f, accy = 0.f;
    int i = s0;
    for (; i + 8 <= s1; i += 8) {
        int sx[8];
#pragma unroll
        for (int u = 0; u < 8; u++) sx[u] = csrc[i + u];
        float ex[8];
#pragma unroll
        for (int u = 0; u < 8; u++) ex[u] = el[sx[u] * N_HEADS + h];
        float2 fx[8];
#pragma unroll
        for (int u = 0; u < 8; u++)
            fx[u] = __half22float2(*(const __half2*)(fb + (size_t)sx[u] * HD));
#pragma unroll
        for (int u = 0; u < 8; u++) {
            float v = ex[u] + erv;
            v = v > 0.f ? v : 0.2f * v;
            float a = __expf(v);
            ssum += a;
            accx += a * fx[u].x;
            accy += a * fx[u].y;
        }
    }
    for (; i < s1; i++) {
        int s = csrc[i];
        float ev = el[s * N_HEADS + h] + erv;
        ev = ev > 0.f ? ev : 0.2f * ev;
        float a = __expf(ev);
        float2 f = __half22float2(*(const __half2*)(fb + (size_t)s * HD));
        ssum += a;
        accx += a * f.x;
        accy += a * f.y;
    }
    float inv = ssum > 0.f ? 1.f / ssum : 0.f;
    if (lane == 0) d_invd[p][dn * N_HEADS + h] = inv;

    float bx = bias[p * HD + h * HIDD + lane * 2];
    float by = bias[p * HD + h * HIDD + lane * 2 + 1];
    float ox = accx * inv + bx, oy = accy * inv + by;
    ox = ox > 0.f ? ox : (__expf(ox) - 1.f);
    oy = oy > 0.f ? oy : (__expf(oy) - 1.f);
    *(float2*)&d_zp[p][(size_t)dn * HD + h * HIDD + lane * 2] = make_float2(ox, oy);
}

// ------------------------------------------------ semantic attention
__global__ void sem_v_kernel(const float* __restrict__ w1,
                             const float* __restrict__ w2,
                             const float* __restrict__ b1) {
    int k = threadIdx.x + blockIdx.x * blockDim.x;
    float s = 0.f;
    for (int j = 0; j < 128; j++) s += w1[k * 128 + j] * w2[j];
    d_v[k] = s;
    if (k == 0) {
        float c = 0.f;
        for (int j = 0; j < 128; j++) c += b1[j] * w2[j];
        d_c = c;
    }
}

__global__ void sem_w_kernel() {
    int gw = (blockIdx.x * blockDim.x + threadIdx.x) >> 5;
    int lane = threadIdx.x & 31;
    int n = gw / P_META;
    int p = gw - n * P_META;
    if (n >= N_NODES) return;
    const float* z = &d_zp[p][(size_t)n * HD];
    float s = 0.f;
#pragma unroll
    for (int k = lane; k < HD; k += 32) s += z[k] * d_v[k];
#pragma unroll
    for (int o = 16; o; o >>= 1) s += __shfl_xor_sync(0xffffffffu, s, o);
    if (lane == 0) {
        float w = s + d_c;
        w = w > 0.f ? w : 0.01f * w;
        atomicAdd(&d_wsum[p], w);
    }
}

__global__ void beta_kernel() {
    if (threadIdx.x == 0) {
        float w0 = d_wsum[0] / (float)N_NODES;
        float w1 = d_wsum[1] / (float)N_NODES;
        float w2 = d_wsum[2] / (float)N_NODES;
        float mx = fmaxf(w0, fmaxf(w1, w2));
        float e0 = expf(w0 - mx), e1 = expf(w1 - mx), e2 = expf(w2 - mx);
        float s = e0 + e1 + e2;
        d_beta[0] = e0 / s;
        d_beta[1] = e1 / s;
        d_beta[2] = e2 / s;
    }
}

// ------------------------------------------------ out = (Σp beta_p zp) @ pred_w + pred_b
// combine_z fused into the epilogue: z computed in-register/smem from zp.
__global__ void out_kernel(const float* __restrict__ pw,
                           const float* __restrict__ pb,
                           float* __restrict__ out) {
    __shared__ float zs[HD];
    int n = blockIdx.x;
    int t = threadIdx.x;   // 64
    float b0 = d_beta[0], b1 = d_beta[1], b2 = d_beta[2];
    for (int k = t; k < HD; k += 64) {
        size_t off = (size_t)n * HD + k;
        zs[k] = b0 * d_zp[0][off] + b1 * d_zp[1][off] + b2 * d_zp[2][off];
    }
    __syncthreads();
    float acc = pb[t];
#pragma unroll 8
    for (int k = 0; k < HD; k++) acc += zs[k] * pw[k * OUT_F + t];
    out[(size_t)n * OUT_F + t] = acc;
}

// ------------------------------------------------ atten scatter (fused alpha)
__global__ void atten_scatter_kernel(const int* __restrict__ src,
                                     const int* __restrict__ dst,
                                     float* __restrict__ atten) {
    int p = blockIdx.y;
    int e = blockIdx.x * blockDim.x + threadIdx.x;
    if (e >= NE) return;
    int s = src[p * NE + e];
    int d = dst[p * NE + e];
    const float* elrow = &d_el[p][s * N_HEADS];
    const float* errow = &d_er[p][d * N_HEADS];
    const float* invrow = &d_invd[p][d * N_HEADS];
    float a = 0.f;
#pragma unroll
    for (int h = 0; h < N_HEADS; h++) {
        float ev = elrow[h] + errow[h];
        ev = ev > 0.f ? ev : 0.2f * ev;
        a += __expf(ev) * invrow[h];
    }
    float v = a * 0.125f * d_beta[p];
    atomicAdd(&atten[(size_t)s * N_NODES + d], v);
}

// ---------------------------------------------------------------- launcher
extern "C" void kernel_launch(void* const* d_in, const int* in_sizes, int n_in,
                              void* d_out, int out_size) {
    const float* h    = (const float*)d_in[0];
    const int*   esrc = (const int*)d_in[1];
    const int*   edst = (const int*)d_in[2];
    const float* fc   = (const float*)d_in[3];
    const float* al   = (const float*)d_in[4];
    const float* ar   = (const float*)d_in[5];
    const float* bias = (const float*)d_in[6];
    const float* w1   = (const float*)d_in[7];
    const float* b1   = (const float*)d_in[8];
    const float* w2   = (const float*)d_in[9];
    const float* pw   = (const float*)d_in[10];
    const float* pb   = (const float*)d_in[11];

    const long long SZ_OUT   = (long long)N_NODES * OUT_F;
    const long long SZ_ATTEN = (long long)N_NODES * N_NODES;
    long long osz = (long long)out_size;

    float* out_ptr = nullptr;
    float* atten_ptr = nullptr;
    if (osz >= SZ_OUT + SZ_ATTEN) {
        out_ptr = (float*)d_out;
        atten_ptr = out_ptr + SZ_OUT;
    } else if (osz == SZ_OUT) {
        out_ptr = (float*)d_out;
    } else if (osz == SZ_ATTEN) {
        atten_ptr = (float*)d_out;
    } else {
        out_ptr = (float*)d_out;
    }

    static cudaStream_t sA = (cudaStream_t)0, sB = (cudaStream_t)0;
    static cudaEvent_t evFork = nullptr, evA = nullptr, evB = nullptr;
    static int streams_ok = -1;
    if (streams_ok < 0) {
        cudaStream_t t1, t2;
        cudaEvent_t e0, e1, e2;
        if (cudaStreamCreateWithFlags(&t1, cudaStreamNonBlocking) == cudaSuccess &&
            cudaStreamCreateWithFlags(&t2, cudaStreamNonBlocking) == cudaSuccess &&
            cudaEventCreateWithFlags(&e0, cudaEventDisableTiming) == cudaSuccess &&
            cudaEventCreateWithFlags(&e1, cudaEventDisableTiming) == cudaSuccess &&
            cudaEventCreateWithFlags(&e2, cudaEventDisableTiming) == cudaSuccess) {
            sA = t1; sB = t2; evFork = e0; evA = e1; evB = e2; streams_ok = 1;
        } else {
            streams_ok = 0;
        }
    }
    cudaStream_t strA = streams_ok ? sA : (cudaStream_t)0;
    cudaStream_t strB = streams_ok ? sB : (cudaStream_t)0;

    if (streams_ok) {
        cudaEventRecord(evFork, (cudaStream_t)0);
        cudaStreamWaitEvent(strA, evFork, 0);
        cudaStreamWaitEvent(strB, evFork, 0);
    }

    // stream A: CSR build chain (joins before aggregate)
    zero_misc_kernel<<<dim3(N_NODES / 256, P_META), 256, 0, strA>>>();
    hist_kernel<<<dim3(NE / 256, P_META), 256, 0, strA>>>(edst);
    scan_kernel<<<P_META, 1024, 0, strA>>>();
    csr_scatter_kernel<<<dim3(NE / 256, P_META), 256, 0, strA>>>(esrc, edst);

    // stream B: atten zero-fill (joins before atten_scatter)
    if (atten_ptr)
        zero_atten_kernel<<<(N_NODES * (N_NODES / 4)) / 256, 256, 0, strB>>>(
            (float4*)atten_ptr);

    // main: GEMM (fp16 out) + el/er
    gemm_feat_kernel<<<dim3(HD / 128, N_NODES / 128, P_META), 256>>>(h, fc);
    eler_kernel<<<dim3(N_NODES, P_META), 256>>>(al, ar);

    if (streams_ok) {
        cudaEventRecord(evA, strA);
        cudaStreamWaitEvent((cudaStream_t)0, evA, 0);
    }

    gat_aggregate_kernel<<<dim3(N_NODES, P_META), 256>>>(bias);

    sem_v_kernel<<<2, 256>>>(w1, w2, b1);
    sem_w_kernel<<<(N_NODES * P_META * 32) / 256, 256>>>();
    beta_kernel<<<1, 32>>>();
    if (out_ptr)
        out_kernel<<<N_NODES, 64>>>(pw, pb, out_ptr);
    if (atten_ptr) {
        if (streams_ok) {
            cudaEventRecord(evB, strB);
            cudaStreamWaitEvent((cudaStream_t)0, evB, 0);
        }
        atten_scatter_kernel<<<dim3(NE / 256, P_META), 256>>>(esrc, edst, atten_ptr);
    }
}

// round 14
// speedup vs baseline: 1.4655x; 1.0254x over previous
#include <cuda_runtime.h>
#include <cuda_fp16.h>
#include <math.h>

#define N_NODES 8192
#define P_META 3
#define IN_F 256
#define HIDD 64
#define N_HEADS 8
#define HD 512
#define OUT_F 64
#define NE 262144

// ---------------- scratch (static device allocations) ----------------
__device__ __half d_feat16[P_META][N_NODES * HD];   // 24 MB (sole feat copy)
__device__ __half d_zp16[P_META][N_NODES * HD];     // 24 MB (fp16 zp)
__device__ float  d_el[P_META][N_NODES * N_HEADS];
__device__ float  d_er[P_META][N_NODES * N_HEADS];
__device__ float  d_invd[P_META][N_NODES * N_HEADS];
__device__ int    d_counts[P_META][N_NODES];
__device__ int    d_cursor[P_META][N_NODES];
__device__ int    d_offsets[P_META][N_NODES + 1];
__device__ int    d_csrsrc[P_META][NE];
__device__ float  d_wsum[P_META];
__device__ float  d_v[HD];
__device__ float  d_c;

// inline beta from wsum (3-way softmax); replaces beta_kernel
__device__ __forceinline__ float3 compute_beta() {
    float w0 = d_wsum[0] * (1.f / (float)N_NODES);
    float w1 = d_wsum[1] * (1.f / (float)N_NODES);
    float w2 = d_wsum[2] * (1.f / (float)N_NODES);
    float mx = fmaxf(w0, fmaxf(w1, w2));
    float e0 = __expf(w0 - mx), e1 = __expf(w1 - mx), e2 = __expf(w2 - mx);
    float inv = 1.f / (e0 + e1 + e2);
    return make_float3(e0 * inv, e1 * inv, e2 * inv);
}

// ---------------------------------------------------------------- utilities
__global__ void zero_misc_kernel() {
    int p = blockIdx.y;
    int i = blockIdx.x * blockDim.x + threadIdx.x;
    if (i < N_NODES) d_counts[p][i] = 0;
    if (p == 0 && i < P_META) d_wsum[i] = 0.f;
}

__global__ void zero_atten_kernel(float4* a) {
    int i = blockIdx.x * blockDim.x + threadIdx.x;
    a[i] = make_float4(0.f, 0.f, 0.f, 0.f);
}

// ------------------------------------------------ feat = h @ fc_p (fp32 GEMM)
__global__ void __launch_bounds__(256, 2)
gemm_feat_kernel(const float* __restrict__ A,    // [8192,256]
                 const float* __restrict__ fc) { // [P,256,512]
    const int p = blockIdx.z;
    const float* __restrict__ B = fc + (size_t)p * IN_F * HD;
    __half* __restrict__ C16 = d_feat16[p];
    __shared__ float As[8][128];
    __shared__ float Bs[8][128];
    const int bm = blockIdx.y * 128;
    const int bn = blockIdx.x * 128;
    const int t = threadIdx.x;
    const int ty = t >> 4, tx = t & 15;

    const int arow = t >> 1;
    const int acol = (t & 1) * 4;
    const int brow = t >> 5;
    const int bcol = (t & 31) * 4;

    float acc[8][8];
#pragma unroll
    for (int i = 0; i < 8; i++)
#pragma unroll
        for (int j = 0; j < 8; j++) acc[i][j] = 0.f;

    for (int k0 = 0; k0 < IN_F; k0 += 8) {
        float4 av = *(const float4*)&A[(size_t)(bm + arow) * IN_F + k0 + acol];
        float4 bv = *(const float4*)&B[(size_t)(k0 + brow) * HD + bn + bcol];
        __syncthreads();
        As[acol + 0][arow] = av.x;
        As[acol + 1][arow] = av.y;
        As[acol + 2][arow] = av.z;
        As[acol + 3][arow] = av.w;
        *(float4*)&Bs[brow][bcol] = bv;
        __syncthreads();
#pragma unroll
        for (int k = 0; k < 8; k++) {
            float a[8], b[8];
            *(float4*)&a[0] = *(const float4*)&As[k][ty * 8];
            *(float4*)&a[4] = *(const float4*)&As[k][ty * 8 + 4];
            *(float4*)&b[0] = *(const float4*)&Bs[k][tx * 8];
            *(float4*)&b[4] = *(const float4*)&Bs[k][tx * 8 + 4];
#pragma unroll
            for (int i = 0; i < 8; i++)
#pragma unroll
                for (int j = 0; j < 8; j++) acc[i][j] += a[i] * b[j];
        }
    }
#pragma unroll
    for (int i = 0; i < 8; i++) {
        size_t roff = (size_t)(bm + ty * 8 + i) * HD + bn + tx * 8;
        __half2* hr = (__half2*)&C16[roff];
        hr[0] = __floats2half2_rn(acc[i][0], acc[i][1]);
        hr[1] = __floats2half2_rn(acc[i][2], acc[i][3]);
        hr[2] = __floats2half2_rn(acc[i][4], acc[i][5]);
        hr[3] = __floats2half2_rn(acc[i][6], acc[i][7]);
    }
}

// ------------------------------------------------ el/er per (node, head, p)
__global__ void eler_kernel(const float* __restrict__ al,
                            const float* __restrict__ ar) {
    int p = blockIdx.y;
    int n = blockIdx.x;
    int h = threadIdx.x >> 5;
    int lane = threadIdx.x & 31;
    float2 f = __half22float2(
        *(const __half2*)&d_feat16[p][(size_t)n * HD + h * HIDD + lane * 2]);
    float2 a = *(const float2*)&al[p * HD + h * HIDD + lane * 2];
    float2 b = *(const float2*)&ar[p * HD + h * HIDD + lane * 2];
    float sl = f.x * a.x + f.y * a.y;
    float sr = f.x * b.x + f.y * b.y;
#pragma unroll
    for (int o = 16; o; o >>= 1) {
        sl += __shfl_xor_sync(0xffffffffu, sl, o);
        sr += __shfl_xor_sync(0xffffffffu, sr, o);
    }
    if (lane == 0) {
        d_el[p][n * N_HEADS + h] = sl;
        d_er[p][n * N_HEADS + h] = sr;
    }
}

// ------------------------------------------------ CSR build by dst
__global__ void hist_kernel(const int* __restrict__ dst) {
    int p = blockIdx.y;
    int e = blockIdx.x * blockDim.x + threadIdx.x;
    if (e < NE) atomicAdd(&d_counts[p][dst[p * NE + e]], 1);
}

__global__ void scan_kernel() {
    int p = blockIdx.x;
    __shared__ int sh[1024];
    int t = threadIdx.x;
    int base = t * 8;
    int loc[8];
    int s = 0;
#pragma unroll
    for (int i = 0; i < 8; i++) { loc[i] = s; s += d_counts[p][base + i]; }
    sh[t] = s;
    __syncthreads();
    for (int ofs = 1; ofs < 1024; ofs <<= 1) {
        int v = (t >= ofs) ? sh[t - ofs] : 0;
        __syncthreads();
        sh[t] += v;
        __syncthreads();
    }
    int pre = (t == 0) ? 0 : sh[t - 1];
#pragma unroll
    for (int i = 0; i < 8; i++) {
        int o = pre + loc[i];
        d_offsets[p][base + i] = o;
        d_cursor[p][base + i] = o;
    }
    if (t == 1023) d_offsets[p][N_NODES] = sh[1023];
}

__global__ void csr_scatter_kernel(const int* __restrict__ src,
                                   const int* __restrict__ dst) {
    int p = blockIdx.y;
    int e = blockIdx.x * blockDim.x + threadIdx.x;
    if (e < NE) {
        int pos = atomicAdd(&d_cursor[p][dst[p * NE + e]], 1);
        d_csrsrc[p][pos] = src[p * NE + e];
    }
}

// ------------------------------------------------ aggregation: one warp per
// (dst, head); single pass, x8 unroll, fp16 gather, fp16 zp store.
__global__ void gat_aggregate_kernel(const float* __restrict__ bias) {
    int p = blockIdx.y;
    int dn = blockIdx.x;
    int h = threadIdx.x >> 5;
    int lane = threadIdx.x & 31;
    int s0 = d_offsets[p][dn], s1 = d_offsets[p][dn + 1];
    float erv = d_er[p][dn * N_HEADS + h];
    const float* __restrict__ el = d_el[p];
    const int* __restrict__ csrc = d_csrsrc[p];
    const __half* fb = &d_feat16[p][h * HIDD + lane * 2];

    float ssum = 0.f, accx = 0.f, accy = 0.f;
    int i = s0;
    for (; i + 8 <= s1; i += 8) {
        int sx[8];
#pragma unroll
        for (int u = 0; u < 8; u++) sx[u] = csrc[i + u];
        float ex[8];
#pragma unroll
        for (int u = 0; u < 8; u++) ex[u] = el[sx[u] * N_HEADS + h];
        float2 fx[8];
#pragma unroll
        for (int u = 0; u < 8; u++)
            fx[u] = __half22float2(*(const __half2*)(fb + (size_t)sx[u] * HD));
#pragma unroll
        for (int u = 0; u < 8; u++) {
            float v = ex[u] + erv;
            v = v > 0.f ? v : 0.2f * v;
            float a = __expf(v);
            ssum += a;
            accx += a * fx[u].x;
            accy += a * fx[u].y;
        }
    }
    for (; i < s1; i++) {
        int s = csrc[i];
        float ev = el[s * N_HEADS + h] + erv;
        ev = ev > 0.f ? ev : 0.2f * ev;
        float a = __expf(ev);
        float2 f = __half22float2(*(const __half2*)(fb + (size_t)s * HD));
        ssum += a;
        accx += a * f.x;
        accy += a * f.y;
    }
    float inv = ssum > 0.f ? 1.f / ssum : 0.f;
    if (lane == 0) d_invd[p][dn * N_HEADS + h] = inv;

    float bx = bias[p * HD + h * HIDD + lane * 2];
    float by = bias[p * HD + h * HIDD + lane * 2 + 1];
    float ox = accx * inv + bx, oy = accy * inv + by;
    ox = ox > 0.f ? ox : (__expf(ox) - 1.f);
    oy = oy > 0.f ? oy : (__expf(oy) - 1.f);
    *(__half2*)&d_zp16[p][(size_t)dn * HD + h * HIDD + lane * 2] =
        __floats2half2_rn(ox, oy);
}

// ------------------------------------------------ semantic attention
__global__ void sem_v_kernel(const float* __restrict__ w1,
                             const float* __restrict__ w2,
                             const float* __restrict__ b1) {
    int k = threadIdx.x + blockIdx.x * blockDim.x;
    float s = 0.f;
    for (int j = 0; j < 128; j++) s += w1[k * 128 + j] * w2[j];
    d_v[k] = s;
    if (k == 0) {
        float c = 0.f;
        for (int j = 0; j < 128; j++) c += b1[j] * w2[j];
        d_c = c;
    }
}

__global__ void sem_w_kernel() {
    int gw = (blockIdx.x * blockDim.x + threadIdx.x) >> 5;
    int lane = threadIdx.x & 31;
    int n = gw / P_META;
    int p = gw - n * P_META;
    if (n >= N_NODES) return;
    const __half* z = &d_zp16[p][(size_t)n * HD];
    float s = 0.f;
#pragma unroll
    for (int k2 = lane; k2 < HD / 2; k2 += 32) {
        float2 f = __half22float2(((const __half2*)z)[k2]);
        s += f.x * d_v[k2 * 2] + f.y * d_v[k2 * 2 + 1];
    }
#pragma unroll
    for (int o = 16; o; o >>= 1) s += __shfl_xor_sync(0xffffffffu, s, o);
    if (lane == 0) {
        float w = s + d_c;
        w = w > 0.f ? w : 0.01f * w;
        atomicAdd(&d_wsum[p], w);
    }
}

// ------------------------------------------------ out = (Σp beta_p zp) @ pred_w + pred_b
__global__ void out_kernel(const float* __restrict__ pw,
                           const float* __restrict__ pb,
                           float* __restrict__ out) {
    __shared__ float zs[HD];
    int n = blockIdx.x;
    int t = threadIdx.x;   // 64
    float3 bt = compute_beta();
    for (int k2 = t; k2 < HD / 2; k2 += 64) {
        size_t off2 = (size_t)n * (HD / 2) + k2;
        float2 a = __half22float2(((const __half2*)d_zp16[0])[off2]);
        float2 b = __half22float2(((const __half2*)d_zp16[1])[off2]);
        float2 c = __half22float2(((const __half2*)d_zp16[2])[off2]);
        zs[k2 * 2]     = bt.x * a.x + bt.y * b.x + bt.z * c.x;
        zs[k2 * 2 + 1] = bt.x * a.y + bt.y * b.y + bt.z * c.y;
    }
    __syncthreads();
    float acc = pb[t];
#pragma unroll 8
    for (int k = 0; k < HD; k++) acc += zs[k] * pw[k * OUT_F + t];
    out[(size_t)n * OUT_F + t] = acc;
}

// ------------------------------------------------ atten scatter (fused alpha+beta)
__global__ void atten_scatter_kernel(const int* __restrict__ src,
                                     const int* __restrict__ dst,
                                     float* __restrict__ atten) {
    int p = blockIdx.y;
    int e = blockIdx.x * blockDim.x + threadIdx.x;
    if (e >= NE) return;
    float3 bt = compute_beta();
    float betap = (p == 0) ? bt.x : (p == 1) ? bt.y : bt.z;
    int s = src[p * NE + e];
    int d = dst[p * NE + e];
    const float* elrow = &d_el[p][s * N_HEADS];
    const float* errow = &d_er[p][d * N_HEADS];
    const float* invrow = &d_invd[p][d * N_HEADS];
    float a = 0.f;
#pragma unroll
    for (int h = 0; h < N_HEADS; h++) {
        float ev = elrow[h] + errow[h];
        ev = ev > 0.f ? ev : 0.2f * ev;
        a += __expf(ev) * invrow[h];
    }
    float v = a * 0.125f * betap;
    atomicAdd(&atten[(size_t)s * N_NODES + d], v);
}

// ---------------------------------------------------------------- launcher
extern "C" void kernel_launch(void* const* d_in, const int* in_sizes, int n_in,
                              void* d_out, int out_size) {
    const float* h    = (const float*)d_in[0];
    const int*   esrc = (const int*)d_in[1];
    const int*   edst = (const int*)d_in[2];
    const float* fc   = (const float*)d_in[3];
    const float* al   = (const float*)d_in[4];
    const float* ar   = (const float*)d_in[5];
    const float* bias = (const float*)d_in[6];
    const float* w1   = (const float*)d_in[7];
    const float* b1   = (const float*)d_in[8];
    const float* w2   = (const float*)d_in[9];
    const float* pw   = (const float*)d_in[10];
    const float* pb   = (const float*)d_in[11];

    const long long SZ_OUT   = (long long)N_NODES * OUT_F;
    const long long SZ_ATTEN = (long long)N_NODES * N_NODES;
    long long osz = (long long)out_size;

    float* out_ptr = nullptr;
    float* atten_ptr = nullptr;
    if (osz >= SZ_OUT + SZ_ATTEN) {
        out_ptr = (float*)d_out;
        atten_ptr = out_ptr + SZ_OUT;
    } else if (osz == SZ_OUT) {
        out_ptr = (float*)d_out;
    } else if (osz == SZ_ATTEN) {
        atten_ptr = (float*)d_out;
    } else {
        out_ptr = (float*)d_out;
    }

    static cudaStream_t sA = (cudaStream_t)0, sB = (cudaStream_t)0;
    static cudaEvent_t evFork = nullptr, evA = nullptr, evC = nullptr, evB = nullptr;
    static int streams_ok = -1;
    if (streams_ok < 0) {
        cudaStream_t t1, t2;
        cudaEvent_t e0, e1, e2, e3;
        if (cudaStreamCreateWithFlags(&t1, cudaStreamNonBlocking) == cudaSuccess &&
            cudaStreamCreateWithFlags(&t2, cudaStreamNonBlocking) == cudaSuccess &&
            cudaEventCreateWithFlags(&e0, cudaEventDisableTiming) == cudaSuccess &&
            cudaEventCreateWithFlags(&e1, cudaEventDisableTiming) == cudaSuccess &&
            cudaEventCreateWithFlags(&e2, cudaEventDisableTiming) == cudaSuccess &&
            cudaEventCreateWithFlags(&e3, cudaEventDisableTiming) == cudaSuccess) {
            sA = t1; sB = t2; evFork = e0; evA = e1; evC = e2; evB = e3;
            streams_ok = 1;
        } else {
            streams_ok = 0;
        }
    }
    cudaStream_t strA = streams_ok ? sA : (cudaStream_t)0;
    cudaStream_t strB = streams_ok ? sB : (cudaStream_t)0;

    if (streams_ok) {
        cudaEventRecord(evFork, (cudaStream_t)0);
        cudaStreamWaitEvent(strA, evFork, 0);
        cudaStreamWaitEvent(strB, evFork, 0);
    }

    // stream A: CSR build chain (joins before aggregate)
    zero_misc_kernel<<<dim3(N_NODES / 256, P_META), 256, 0, strA>>>();
    hist_kernel<<<dim3(NE / 256, P_META), 256, 0, strA>>>(edst);
    scan_kernel<<<P_META, 1024, 0, strA>>>();
    csr_scatter_kernel<<<dim3(NE / 256, P_META), 256, 0, strA>>>(esrc, edst);

    // stream B: atten zero-fill
    if (atten_ptr)
        zero_atten_kernel<<<(N_NODES * (N_NODES / 4)) / 256, 256, 0, strB>>>(
            (float4*)atten_ptr);

    // main: GEMM (fp16 out) + el/er
    gemm_feat_kernel<<<dim3(HD / 128, N_NODES / 128, P_META), 256>>>(h, fc);
    eler_kernel<<<dim3(N_NODES, P_META), 256>>>(al, ar);

    if (streams_ok) {
        cudaEventRecord(evA, strA);
        cudaStreamWaitEvent((cudaStream_t)0, evA, 0);
    }

    gat_aggregate_kernel<<<dim3(N_NODES, P_META), 256>>>(bias);

    sem_v_kernel<<<2, 256>>>(w1, w2, b1);
    sem_w_kernel<<<(N_NODES * P_META * 32) / 256, 256>>>();

    if (atten_ptr && streams_ok) {
        // atten_scatter on stream B, concurrent with out_kernel on main
        cudaEventRecord(evC, (cudaStream_t)0);   // after sem_w (wsum ready)
        cudaStreamWaitEvent(strB, evC, 0);
        atten_scatter_kernel<<<dim3(NE / 256, P_META), 256, 0, strB>>>(
            esrc, edst, atten_ptr);
        cudaEventRecord(evB, strB);
    }

    if (out_ptr)
        out_kernel<<<N_NODES, 64>>>(pw, pb, out_ptr);

    if (atten_ptr) {
        if (streams_ok) {
            cudaStreamWaitEvent((cudaStream_t)0, evB, 0);   // join B -> main
        } else {
            atten_scatter_kernel<<<dim3(NE / 256, P_META), 256>>>(esrc, edst,
                                                                  atten_ptr);
        }
    }
    // join stream A as well (already joined pre-aggregate; nothing pending)
}